// round 6
// baseline (speedup 1.0000x reference)
#include <cuda_runtime.h>
#include <cstdint>

#define NSAMPLES   524288
#define NFEAT      64
#define NGATES     64
#define NOUT       8
#define BASEN      66            // NFEAT + const0 + const1
#define MAXCONN    130
#define BLK        128           // threads per block = samples per block
#define EST        132           // entry stride in floats (mult of 4 -> STS.128 legal)
#define ROWB       (EST * 4)     // 528 bytes per entry row
#define CAP        108           // compact capacity (slots); 4 blocks/SM
#define SMEM_FAST  (CAP * ROWB)      // 57024 B
#define SMEM_FULL  (MAXCONN * ROWB)  // 68640 B (fallback)

// Slots: 0 = trash (write-only), 1 = const0, 2 = const1, 3.. = compacted entries.
struct Params {
    uint4    goff[NGATES];   // {byteA, byteB, byteStore, 0} compact offsets
    uint2    forig[NGATES];  // {byteA, byteB} original-index offsets (fallback)
    unsigned xoff[NFEAT];    // compact byte offset per X feature (0 = skip/trash)
    unsigned flags;          // 1 = overflow -> fallback kernel runs
    unsigned pad[3];         // align w to 16B
    float    w[NGATES][NOUT];// output_weights * output_scale
};
__device__   Params g_stage;
__constant__ Params c_p;

__device__ int s_i1[NGATES], s_i2[NGATES];

// ---------------------------------------------------------------------------
// Prep: top-2 (softmax-monotonic, top_k tie-break) + compaction + weight fold.
// ---------------------------------------------------------------------------
__global__ void __launch_bounds__(1024)
prep_kernel(const float* __restrict__ gw,
            const float* __restrict__ ow,
            const float* __restrict__ sc) {
    const int tid  = threadIdx.x;
    const int gate = tid >> 4;
    const int lane = tid & 15;
    const float* row = gw + gate * MAXCONN;
    const int n = BASEN + gate;

    float v1 = -3.4e38f, v2 = -3.4e38f;
    int   i1 = 0x7fffffff, i2 = 0x7fffffff;
#pragma unroll
    for (int k = 0; k < (MAXCONN + 15) / 16; ++k) {
        int j = lane + k * 16;
        if (j < n) {
            float v = row[j];
            if (v > v1 || (v == v1 && j < i1)) { v2 = v1; i2 = i1; v1 = v; i1 = j; }
            else if (v > v2 || (v == v2 && j < i2)) { v2 = v; i2 = j; }
        }
    }
#pragma unroll
    for (int d = 8; d >= 1; d >>= 1) {
        float ov1 = __shfl_down_sync(0xffffffffu, v1, d);
        int   oi1 = __shfl_down_sync(0xffffffffu, i1, d);
        float ov2 = __shfl_down_sync(0xffffffffu, v2, d);
        int   oi2 = __shfl_down_sync(0xffffffffu, i2, d);
        if (ov1 > v1 || (ov1 == v1 && oi1 < i1)) { v2 = v1; i2 = i1; v1 = ov1; i1 = oi1; }
        else if (ov1 > v2 || (ov1 == v2 && oi1 < i2)) { v2 = ov1; i2 = oi1; }
        if (ov2 > v1 || (ov2 == v1 && oi2 < i1)) { v2 = v1; i2 = i1; v1 = ov2; i1 = oi2; }
        else if (ov2 > v2 || (ov2 == v2 && oi2 < i2)) { v2 = ov2; i2 = oi2; }
    }
    if (lane == 0) { s_i1[gate] = i1; s_i2[gate] = i2; }

    if (tid < NGATES * NOUT) {
        int i = tid >> 3, j = tid & 7;
        g_stage.w[i][j] = ow[i * NOUT + j] * sc[j];
    }
    __syncthreads();

    // Serial compaction (tiny): mark referenced entries, assign slots.
    if (tid == 0) {
        bool need[MAXCONN];
        for (int e = 0; e < MAXCONN; ++e) need[e] = false;
        for (int g = 0; g < NGATES; ++g) { need[s_i1[g]] = true; need[s_i2[g]] = true; }

        int slot[MAXCONN];
        int next = 3;
        for (int e = 0; e < MAXCONN; ++e) {
            if (e == 64)      slot[e] = 1;               // const 0
            else if (e == 65) slot[e] = 2;               // const 1
            else if (need[e]) slot[e] = next++;
            else              slot[e] = 0;               // trash
        }
        g_stage.flags = (next > CAP) ? 1u : 0u;

        for (int g = 0; g < NGATES; ++g) {
            g_stage.goff[g] = make_uint4((unsigned)(slot[s_i1[g]] * ROWB),
                                         (unsigned)(slot[s_i2[g]] * ROWB),
                                         (unsigned)(slot[BASEN + g] * ROWB), 0u);
            g_stage.forig[g] = make_uint2((unsigned)(s_i1[g] * ROWB),
                                          (unsigned)(s_i2[g] * ROWB));
        }
        for (int f = 0; f < NFEAT; ++f)
            g_stage.xoff[f] = (unsigned)(slot[f] * ROWB);
    }
}

// ---------------------------------------------------------------------------
// Fast path: compacted smem buffer (CAP rows), 4 blocks/SM -> 16 warps/SM.
// Transpose: 16x LDG.128 -> register quad transpose -> predicated STS.128
// (skipping never-read features). Gate loop: 2 LDS + 1 STS + packed-f32x2
// accumulation (5 FMA-pipe ops / gate instead of 9).
// ---------------------------------------------------------------------------
__global__ void __launch_bounds__(BLK, 4)
fast_kernel(const float* __restrict__ X, float* __restrict__ out) {
    if (c_p.flags) return;
    extern __shared__ float sbuf[];
    char* sb = (char*)sbuf;
    const int tid = threadIdx.x;
    const long long base = (long long)blockIdx.x * BLK;

    // --- X transpose into compact slots ---
    {
        const int c = tid & 15;          // 16B chunk -> features 4c..4c+3
        const int q = tid >> 4;          // 0..7
        const float4* Xb = (const float4*)(X + base * NFEAT);
        unsigned xo0 = c_p.xoff[4 * c + 0];
        unsigned xo1 = c_p.xoff[4 * c + 1];
        unsigned xo2 = c_p.xoff[4 * c + 2];
        unsigned xo3 = c_p.xoff[4 * c + 3];
#pragma unroll
        for (int r = 0; r < 4; ++r) {
            int sq = q + 8 * r;                       // sample-quad 0..31
            const float4* rp = Xb + (4 * sq) * 16 + c;
            float4 v0 = __ldcs(rp + 0 * 16);
            float4 v1 = __ldcs(rp + 1 * 16);
            float4 v2 = __ldcs(rp + 2 * 16);
            float4 v3 = __ldcs(rp + 3 * 16);
            unsigned so = 16u * sq;
            if (xo0) *(float4*)(sb + xo0 + so) = make_float4(v0.x, v1.x, v2.x, v3.x);
            if (xo1) *(float4*)(sb + xo1 + so) = make_float4(v0.y, v1.y, v2.y, v3.y);
            if (xo2) *(float4*)(sb + xo2 + so) = make_float4(v0.z, v1.z, v2.z, v3.z);
            if (xo3) *(float4*)(sb + xo3 + so) = make_float4(v0.w, v1.w, v2.w, v3.w);
        }
    }
    ((float*)(sb + 1 * ROWB))[tid] = 0.0f;   // const 0 row
    ((float*)(sb + 2 * ROWB))[tid] = 1.0f;   // const 1 row
    __syncthreads();

    const unsigned m4 = 4u * tid;
    unsigned long long acc01 = 0, acc23 = 0, acc45 = 0, acc67 = 0;

    uint4 o = c_p.goff[0];
    float a = *(const float*)(sb + o.x + m4);
    float b = *(const float*)(sb + o.y + m4);

#pragma unroll
    for (int i = 0; i < NGATES; ++i) {
        float g = fmaf(-a, b, 1.0f);
        *(float*)(sb + o.z + m4) = g;            // STS (trash slot if unused)

        if (i + 1 < NGATES) {                    // post-STS prefetch, never stale
            uint4 on = c_p.goff[i + 1];
            a = *(const float*)(sb + on.x + m4);
            b = *(const float*)(sb + on.y + m4);
            o = on;
        }

        unsigned long long gg;
        asm("mov.b64 %0, {%1, %1};" : "=l"(gg) : "f"(g));
        const ulonglong2* wp = (const ulonglong2*)&c_p.w[i][0];
        ulonglong2 wA = wp[0], wB = wp[1];
        asm("fma.rn.f32x2 %0, %1, %2, %0;" : "+l"(acc01) : "l"(gg), "l"(wA.x));
        asm("fma.rn.f32x2 %0, %1, %2, %0;" : "+l"(acc23) : "l"(gg), "l"(wA.y));
        asm("fma.rn.f32x2 %0, %1, %2, %0;" : "+l"(acc45) : "l"(gg), "l"(wB.x));
        asm("fma.rn.f32x2 %0, %1, %2, %0;" : "+l"(acc67) : "l"(gg), "l"(wB.y));
    }

    float a0, a1, a2, a3, a4, a5, a6, a7;
    asm("mov.b64 {%0, %1}, %2;" : "=f"(a0), "=f"(a1) : "l"(acc01));
    asm("mov.b64 {%0, %1}, %2;" : "=f"(a2), "=f"(a3) : "l"(acc23));
    asm("mov.b64 {%0, %1}, %2;" : "=f"(a4), "=f"(a5) : "l"(acc45));
    asm("mov.b64 {%0, %1}, %2;" : "=f"(a6), "=f"(a7) : "l"(acc67));
    float4* op = (float4*)(out + (base + tid) * NOUT);
    __stcs(&op[0], make_float4(a0, a1, a2, a3));
    __stcs(&op[1], make_float4(a4, a5, a6, a7));
}

// ---------------------------------------------------------------------------
// Fallback (overflow only): full 130-row buffer, original indices. R4-proven
// structure; runs only if compaction exceeds CAP (prob ~0 for this dataset).
// ---------------------------------------------------------------------------
__global__ void __launch_bounds__(BLK, 3)
full_kernel(const float* __restrict__ X, float* __restrict__ out) {
    if (!c_p.flags) return;
    extern __shared__ float sbuf[];
    char* sb = (char*)sbuf;
    const int tid = threadIdx.x;
    const long long base = (long long)blockIdx.x * BLK;

    const float4* Xb = (const float4*)(X + base * NFEAT);
#pragma unroll
    for (int k = 0; k < NFEAT / 4; ++k) {
        float4 v = __ldcs(&Xb[k * BLK + tid]);
        int e = 4 * (k * BLK + tid);
        int s = e >> 6;
        int f = e & 63;
        sbuf[(f + 0) * EST + s] = v.x;
        sbuf[(f + 1) * EST + s] = v.y;
        sbuf[(f + 2) * EST + s] = v.z;
        sbuf[(f + 3) * EST + s] = v.w;
    }
    sbuf[64 * EST + tid] = 0.0f;
    sbuf[65 * EST + tid] = 1.0f;
    __syncthreads();

    const unsigned m4 = 4u * tid;
    float acc[NOUT];
#pragma unroll
    for (int j = 0; j < NOUT; ++j) acc[j] = 0.0f;

    uint2 o0 = c_p.forig[0];
    float a = *(const float*)(sb + o0.x + m4);
    float b = *(const float*)(sb + o0.y + m4);

#pragma unroll
    for (int i = 0; i < NGATES; ++i) {
        float g = fmaf(-a, b, 1.0f);
        *(float*)(sb + (unsigned)((BASEN + i) * ROWB) + m4) = g;
        if (i + 1 < NGATES) {
            uint2 o = c_p.forig[i + 1];
            a = *(const float*)(sb + o.x + m4);
            b = *(const float*)(sb + o.y + m4);
        }
        float4 w0 = *(const float4*)&c_p.w[i][0];
        float4 w1 = *(const float4*)&c_p.w[i][4];
        acc[0] = fmaf(g, w0.x, acc[0]);
        acc[1] = fmaf(g, w0.y, acc[1]);
        acc[2] = fmaf(g, w0.z, acc[2]);
        acc[3] = fmaf(g, w0.w, acc[3]);
        acc[4] = fmaf(g, w1.x, acc[4]);
        acc[5] = fmaf(g, w1.y, acc[5]);
        acc[6] = fmaf(g, w1.z, acc[6]);
        acc[7] = fmaf(g, w1.w, acc[7]);
    }
    float4* op = (float4*)(out + (base + tid) * NOUT);
    __stcs(&op[0], make_float4(acc[0], acc[1], acc[2], acc[3]));
    __stcs(&op[1], make_float4(acc[4], acc[5], acc[6], acc[7]));
}

// ---------------------------------------------------------------------------
// Launch: prep -> one constant memcpy -> fast + guarded fallback (4 nodes).
// ---------------------------------------------------------------------------
extern "C" void kernel_launch(void* const* d_in, const int* in_sizes, int n_in,
                              void* d_out, int out_size) {
    const float* X  = (const float*)d_in[0];
    const float* gw = (const float*)d_in[1];
    const float* ow = (const float*)d_in[2];
    const float* sc = (const float*)d_in[3];
    float* out = (float*)d_out;

    cudaFuncSetAttribute((const void*)fast_kernel,
                         cudaFuncAttributeMaxDynamicSharedMemorySize, SMEM_FAST);
    cudaFuncSetAttribute((const void*)full_kernel,
                         cudaFuncAttributeMaxDynamicSharedMemorySize, SMEM_FULL);

    prep_kernel<<<1, 1024>>>(gw, ow, sc);

    void* gp = nullptr;
    cudaGetSymbolAddress(&gp, g_stage);
    cudaMemcpyToSymbolAsync(c_p, gp, sizeof(Params), 0,
                            cudaMemcpyDeviceToDevice, 0);

    fast_kernel<<<NSAMPLES / BLK, BLK, SMEM_FAST>>>(X, out);
    full_kernel<<<NSAMPLES / BLK, BLK, SMEM_FULL>>>(X, out);
}

// round 8
// speedup vs baseline: 1.0987x; 1.0987x over previous
#include <cuda_runtime.h>
#include <cuda_fp16.h>
#include <cstdint>

#define NSAMPLES   524288
#define NFEAT      64
#define NGATES     64
#define NOUT       8
#define BASEN      66            // NFEAT + const0 + const1
#define MAXCONN    130
#define BLK        128           // threads per block
#define SPB        256           // samples per block (2 per thread, half2)
#define ROWB       512           // bytes per entry row: 256 samples * 2B
#define CAP        108           // compact slot capacity -> 4 blocks/SM
#define SMEM_FAST  (CAP * ROWB)      // 55296 B
#define FEST       132               // fallback fp32 row stride (floats)
#define FROWB      (FEST * 4)
#define SMEM_FULL  (MAXCONN * FROWB) // 68640 B

// XOR swizzle keyed on ORIGINAL entry index e (consistent for writer+reader):
//   phys_off = logical_off ^ (8 * ((e>>2) & 15))
// Gate LDS.32/STS.32: warp reads a contiguous 128B block; XOR permutes within
// it -> 1 wavefront, conflict-free. Transpose STS.64: swz = 8c (c = feature
// chunk) is injective across the 16 c-lanes -> 32 lanes tile 128B x2, CF.

struct Params {
    uint4    goff[NGATES];      // {byteA, swzA, byteB, swzB}
    unsigned gstore[NGATES];    // store-row byte offset; 0 = dead gate (skip STS)
    uint2    forig[NGATES];     // fallback fp32 offsets (original indices)
    unsigned xoff[NFEAT];       // X feature row byte offset; 0 = dead (skip)
    unsigned flags;             // 1 = overflow -> fallback runs
    unsigned pad;
    float2   w2[NGATES][NOUT];  // (w,w) duplicated for f32x2 FMA
    float    w1[NGATES][NOUT];  // scalar weights for fallback
};
__device__   Params g_stage;
__constant__ Params c_p;

// ---------------------------------------------------------------------------
// Prep: top-2 (softmax monotonic => top-2 of raw masked logits; lexicographic
// compare reproduces top_k tie-break), fully parallel slot compaction
// (ballot+popc scan, all in smem), weight folding. No serial global walks.
// ---------------------------------------------------------------------------
__global__ void __launch_bounds__(1024)
prep_kernel(const float* __restrict__ gw,
            const float* __restrict__ ow,
            const float* __restrict__ sc) {
    __shared__ int si1[NGATES], si2[NGATES];
    __shared__ int slotArr[MAXCONN];
    __shared__ unsigned char needf[MAXCONN];

    const int tid  = threadIdx.x;
    const int gate = tid >> 4;
    const int lane = tid & 15;

    if (tid < MAXCONN) needf[tid] = 0;

    const float* row = gw + gate * MAXCONN;
    const int n = BASEN + gate;
    float v1 = -3.4e38f, v2 = -3.4e38f;
    int   i1 = 0x7fffffff, i2 = 0x7fffffff;
#pragma unroll
    for (int k = 0; k < (MAXCONN + 15) / 16; ++k) {
        int j = lane + k * 16;
        if (j < n) {
            float v = row[j];
            if (v > v1 || (v == v1 && j < i1)) { v2 = v1; i2 = i1; v1 = v; i1 = j; }
            else if (v > v2 || (v == v2 && j < i2)) { v2 = v; i2 = j; }
        }
    }
#pragma unroll
    for (int d = 8; d >= 1; d >>= 1) {
        float ov1 = __shfl_down_sync(0xffffffffu, v1, d);
        int   oi1 = __shfl_down_sync(0xffffffffu, i1, d);
        float ov2 = __shfl_down_sync(0xffffffffu, v2, d);
        int   oi2 = __shfl_down_sync(0xffffffffu, i2, d);
        if (ov1 > v1 || (ov1 == v1 && oi1 < i1)) { v2 = v1; i2 = i1; v1 = ov1; i1 = oi1; }
        else if (ov1 > v2 || (ov1 == v2 && oi1 < i2)) { v2 = ov1; i2 = oi1; }
        if (ov2 > v1 || (ov2 == v1 && oi2 < i1)) { v2 = v1; i2 = i1; v1 = ov2; i1 = oi2; }
        else if (ov2 > v2 || (ov2 == v2 && oi2 < i2)) { v2 = ov2; i2 = oi2; }
    }
    if (lane == 0) { si1[gate] = i1; si2[gate] = i2; }
    __syncthreads();

    if (tid < NGATES) { needf[si1[tid]] = 1; needf[si2[tid]] = 1; }
    __syncthreads();

    if (tid < 32) {                       // warp-parallel prefix compaction
        int running = 3;                  // slot 0 trash, 1 const0, 2 const1
        for (int ch = 0; ch < 5; ++ch) {
            int e = ch * 32 + tid;
            bool nd = (e < MAXCONN) && needf[e] && (e != 64) && (e != 65);
            unsigned mask = __ballot_sync(0xffffffffu, nd);
            if (e < MAXCONN) {
                int s;
                if      (e == 64) s = 1;
                else if (e == 65) s = 2;
                else if (nd)      s = running + __popc(mask & ((1u << tid) - 1u));
                else              s = 0;
                slotArr[e] = s;
            }
            running += __popc(mask);
        }
        if (tid == 0) g_stage.flags = (running > CAP) ? 1u : 0u;
    }
    __syncthreads();

    if (tid < NGATES) {
        int e1 = si1[tid], e2 = si2[tid];
        g_stage.goff[tid] = make_uint4((unsigned)(slotArr[e1] * ROWB),
                                       8u * (unsigned)((e1 >> 2) & 15),
                                       (unsigned)(slotArr[e2] * ROWB),
                                       8u * (unsigned)((e2 >> 2) & 15));
        g_stage.gstore[tid] = (unsigned)(slotArr[BASEN + tid] * ROWB);
        g_stage.forig[tid]  = make_uint2((unsigned)(e1 * FROWB),
                                         (unsigned)(e2 * FROWB));
    }
    if (tid < NFEAT)
        g_stage.xoff[tid] = (unsigned)(slotArr[tid] * ROWB);
    if (tid < NGATES * NOUT) {
        int i = tid >> 3, j = tid & 7;
        float wv = ow[i * NOUT + j] * sc[j];
        g_stage.w2[i][j] = make_float2(wv, wv);
        g_stage.w1[i][j] = wv;
    }
}

static __device__ __forceinline__ unsigned pack_h2(float a, float b) {
    __half2 h = __floats2half2_rn(a, b);
    __half2_raw r = *reinterpret_cast<__half2_raw*>(&h);
    return (unsigned)r.x | ((unsigned)r.y << 16);
}

// ---------------------------------------------------------------------------
// Fast path: fp16 buffer, 2 samples/thread. Compute fp32, store half2.
// Warp covers 64 samples; per gate: 2 LDS.32 (1 wf each) + predicated STS.32
// (skipped for the ~58% of gates never read). X transpose: LDG.128 quads ->
// fp16 pack -> STS.64, conflict-free via the entry-index XOR swizzle.
// ---------------------------------------------------------------------------
__global__ void __launch_bounds__(BLK, 4)
fast_kernel(const float* __restrict__ X, float* __restrict__ out) {
    if (c_p.flags) return;
    extern __shared__ char sb[];
    const int tid = threadIdx.x;
    const long long base = (long long)blockIdx.x * SPB;

    // --- X transpose: warp wq handles samples 64wq..64wq+63 ---
    {
        const int c  = tid & 15;          // feature chunk: features 4c..4c+3
        const int h  = (tid >> 4) & 1;
        const int wq = tid >> 5;
        const float4* Xb = (const float4*)(X + base * NFEAT);
        unsigned xo0 = c_p.xoff[4 * c + 0];
        unsigned xo1 = c_p.xoff[4 * c + 1];
        unsigned xo2 = c_p.xoff[4 * c + 2];
        unsigned xo3 = c_p.xoff[4 * c + 3];
        const unsigned swz = 8u * (unsigned)c;    // swz(4c+f) = 8c
#pragma unroll
        for (int r = 0; r < 8; ++r) {
            int sq = 16 * wq + 8 * h + r;         // sample quad 0..63
            const float4* rp = Xb + (4 * sq) * 16 + c;
            float4 v0 = __ldcs(rp + 0 * 16);
            float4 v1 = __ldcs(rp + 1 * 16);
            float4 v2 = __ldcs(rp + 2 * 16);
            float4 v3 = __ldcs(rp + 3 * 16);
            unsigned so = (8u * (unsigned)sq) ^ swz;
            if (xo0) *(uint2*)(sb + xo0 + so) =
                make_uint2(pack_h2(v0.x, v1.x), pack_h2(v2.x, v3.x));
            if (xo1) *(uint2*)(sb + xo1 + so) =
                make_uint2(pack_h2(v0.y, v1.y), pack_h2(v2.y, v3.y));
            if (xo2) *(uint2*)(sb + xo2 + so) =
                make_uint2(pack_h2(v0.z, v1.z), pack_h2(v2.z, v3.z));
            if (xo3) *(uint2*)(sb + xo3 + so) =
                make_uint2(pack_h2(v0.w, v1.w), pack_h2(v2.w, v3.w));
        }
    }
    const unsigned m = 4u * tid;          // this thread's pair offset (bytes)
    *(__half2*)(sb + 1 * ROWB + m) = __floats2half2_rn(0.0f, 0.0f); // swz=0
    *(__half2*)(sb + 2 * ROWB + m) = __floats2half2_rn(1.0f, 1.0f); // swz=0
    __syncthreads();

    unsigned long long acc[NOUT];
#pragma unroll
    for (int j = 0; j < NOUT; ++j) acc[j] = 0ULL;

    uint4 o = c_p.goff[0];
    __half2 ah = *(const __half2*)(sb + o.x + (m ^ o.y));
    __half2 bh = *(const __half2*)(sb + o.z + (m ^ o.w));

#pragma unroll
    for (int i = 0; i < NGATES; ++i) {
        float2 af = __half22float2(ah);
        float2 bf = __half22float2(bh);
        float gx = fmaf(-af.x, bf.x, 1.0f);
        float gy = fmaf(-af.y, bf.y, 1.0f);

        unsigned os = c_p.gstore[i];      // 0 => gate never read: skip STS
        const unsigned swzS = 8u * (unsigned)(((BASEN + i) >> 2) & 15);
        if (os) *(__half2*)(sb + os + (m ^ swzS)) = __floats2half2_rn(gx, gy);

        if (i + 1 < NGATES) {             // post-STS prefetch: never stale
            o = c_p.goff[i + 1];
            ah = *(const __half2*)(sb + o.x + (m ^ o.y));
            bh = *(const __half2*)(sb + o.z + (m ^ o.w));
        }

        unsigned long long gg;
        asm("mov.b64 %0, {%1, %2};" : "=l"(gg) : "f"(gx), "f"(gy));
        const unsigned long long* wp = (const unsigned long long*)&c_p.w2[i][0];
#pragma unroll
        for (int j = 0; j < NOUT; ++j)
            asm("fma.rn.f32x2 %0, %1, %2, %0;" : "+l"(acc[j]) : "l"(gg), "l"(wp[j]));
    }

    float s0[NOUT], s1[NOUT];
#pragma unroll
    for (int j = 0; j < NOUT; ++j)
        asm("mov.b64 {%0, %1}, %2;" : "=f"(s0[j]), "=f"(s1[j]) : "l"(acc[j]));
    float4* op = (float4*)(out + (base + 2 * tid) * NOUT);
    __stcs(&op[0], make_float4(s0[0], s0[1], s0[2], s0[3]));
    __stcs(&op[1], make_float4(s0[4], s0[5], s0[6], s0[7]));
    __stcs(&op[2], make_float4(s1[0], s1[1], s1[2], s1[3]));
    __stcs(&op[3], make_float4(s1[4], s1[5], s1[6], s1[7]));
}

// ---------------------------------------------------------------------------
// Fallback (CAP overflow only; never for this dataset): full fp32 buffer.
// ---------------------------------------------------------------------------
__global__ void __launch_bounds__(128, 3)
full_kernel(const float* __restrict__ X, float* __restrict__ out) {
    if (!c_p.flags) return;
    extern __shared__ float sbuf[];
    char* sb = (char*)sbuf;
    const int tid = threadIdx.x;
    const long long base = (long long)blockIdx.x * 128;

    const float4* Xb = (const float4*)(X + base * NFEAT);
#pragma unroll
    for (int k = 0; k < NFEAT / 4; ++k) {
        float4 v = __ldcs(&Xb[k * 128 + tid]);
        int e = 4 * (k * 128 + tid);
        int s = e >> 6;
        int f = e & 63;
        sbuf[(f + 0) * FEST + s] = v.x;
        sbuf[(f + 1) * FEST + s] = v.y;
        sbuf[(f + 2) * FEST + s] = v.z;
        sbuf[(f + 3) * FEST + s] = v.w;
    }
    sbuf[64 * FEST + tid] = 0.0f;
    sbuf[65 * FEST + tid] = 1.0f;
    __syncthreads();

    const unsigned m4 = 4u * tid;
    float acc[NOUT];
#pragma unroll
    for (int j = 0; j < NOUT; ++j) acc[j] = 0.0f;

    uint2 o0 = c_p.forig[0];
    float a = *(const float*)(sb + o0.x + m4);
    float b = *(const float*)(sb + o0.y + m4);

#pragma unroll
    for (int i = 0; i < NGATES; ++i) {
        float g = fmaf(-a, b, 1.0f);
        *(float*)(sb + (unsigned)((BASEN + i) * FROWB) + m4) = g;
        if (i + 1 < NGATES) {
            uint2 o = c_p.forig[i + 1];
            a = *(const float*)(sb + o.x + m4);
            b = *(const float*)(sb + o.y + m4);
        }
#pragma unroll
        for (int j = 0; j < NOUT; ++j)
            acc[j] = fmaf(g, c_p.w1[i][j], acc[j]);
    }
    float4* op = (float4*)(out + (base + tid) * NOUT);
    __stcs(&op[0], make_float4(acc[0], acc[1], acc[2], acc[3]));
    __stcs(&op[1], make_float4(acc[4], acc[5], acc[6], acc[7]));
}

// ---------------------------------------------------------------------------
// Launch: prep -> one constant memcpy -> fast + guarded fallback (4 nodes).
// ---------------------------------------------------------------------------
extern "C" void kernel_launch(void* const* d_in, const int* in_sizes, int n_in,
                              void* d_out, int out_size) {
    const float* X  = (const float*)d_in[0];
    const float* gw = (const float*)d_in[1];
    const float* ow = (const float*)d_in[2];
    const float* sc = (const float*)d_in[3];
    float* out = (float*)d_out;

    cudaFuncSetAttribute((const void*)fast_kernel,
                         cudaFuncAttributeMaxDynamicSharedMemorySize, SMEM_FAST);
    cudaFuncSetAttribute((const void*)full_kernel,
                         cudaFuncAttributeMaxDynamicSharedMemorySize, SMEM_FULL);

    prep_kernel<<<1, 1024>>>(gw, ow, sc);

    void* gp = nullptr;
    cudaGetSymbolAddress(&gp, g_stage);
    cudaMemcpyToSymbolAsync(c_p, gp, sizeof(Params), 0,
                            cudaMemcpyDeviceToDevice, 0);

    fast_kernel<<<NSAMPLES / SPB, BLK, SMEM_FAST>>>(X, out);
    full_kernel<<<NSAMPLES / 128, 128, SMEM_FULL>>>(X, out);
}

// round 9
// speedup vs baseline: 1.2316x; 1.1210x over previous
#include <cuda_runtime.h>
#include <cuda_fp16.h>
#include <cstdint>

#define NSAMPLES   524288
#define NFEAT      64
#define NGATES     64
#define NOUT       8
#define BASEN      66
#define MAXCONN    130
#define BLK        128           // threads per block
#define SPB        256           // samples per tile (2 per thread, half2)
#define ROWB       512           // bytes per entry row (256 samples * 2B)
#define CAPX       57            // live X feature rows (cap)
#define CAPG       30            // live gate rows (cap)
#define GROW0      3             // rows: 0 trash, 1 const0, 2 const1, 3.. gates
#define XROW0      (GROW0 + CAPG)        // 33: X buffer0 start row
#define XSZB       (CAPX * ROWB)         // 29184 B per X buffer
#define SMEM_FAST  ((XROW0 + 2 * CAPX) * ROWB)   // 147 rows = 75264 B -> 3 blocks/SM
#define NT         (NSAMPLES / SPB)      // 2048 tiles
#define GRID_FAST  444                   // 148 SMs * 3 persistent blocks

#define FEST       132
#define FROWB      (FEST * 4)
#define SMEM_FULL  (MAXCONN * FROWB)
#define NTF        (NSAMPLES / 128)
#define GRID_FULL  444

// XOR swizzle keyed on ORIGINAL entry index e:  phys = logical ^ (8*((e>>2)&15))
// (same scheme as R8, verified correct/conflict-free there).

struct Params {
    uint4    goff[NGATES];      // {offA | isX, swzA, offB | isX, swzB}  (buffer-0 based)
    unsigned gstore[NGATES];    // gate row byte offset; 0 = dead gate (skip STS)
    uint2    forig[NGATES];     // fallback fp32 offsets
    unsigned xoff[NFEAT];       // X row byte offset (buffer-0); 0 = dead feature
    unsigned flags;             // 1 = overflow -> fallback runs
    unsigned pad;
    float2   w2[NGATES][NOUT];  // (w,w) for f32x2 FMA
    float    w1[NGATES][NOUT];  // scalar weights for fallback
};
__device__   Params g_stage;
__constant__ Params c_p;

// ---------------------------------------------------------------------------
// Prep: top-2 of masked logits (softmax monotonic; lexicographic tie-break),
// two-pool compaction (X rows, gate rows), weight fold. All parallel.
// ---------------------------------------------------------------------------
__global__ void __launch_bounds__(1024)
prep_kernel(const float* __restrict__ gw,
            const float* __restrict__ ow,
            const float* __restrict__ sc) {
    __shared__ int si1[NGATES], si2[NGATES];
    __shared__ int xrowA[NFEAT], growA[NGATES];
    __shared__ unsigned char needf[MAXCONN];

    const int tid  = threadIdx.x;
    const int gate = tid >> 4;
    const int lane = tid & 15;

    if (tid < MAXCONN) needf[tid] = 0;

    const float* row = gw + gate * MAXCONN;
    const int n = BASEN + gate;
    float v1 = -3.4e38f, v2 = -3.4e38f;
    int   i1 = 0x7fffffff, i2 = 0x7fffffff;
#pragma unroll
    for (int k = 0; k < (MAXCONN + 15) / 16; ++k) {
        int j = lane + k * 16;
        if (j < n) {
            float v = row[j];
            if (v > v1 || (v == v1 && j < i1)) { v2 = v1; i2 = i1; v1 = v; i1 = j; }
            else if (v > v2 || (v == v2 && j < i2)) { v2 = v; i2 = j; }
        }
    }
#pragma unroll
    for (int d = 8; d >= 1; d >>= 1) {
        float ov1 = __shfl_down_sync(0xffffffffu, v1, d);
        int   oi1 = __shfl_down_sync(0xffffffffu, i1, d);
        float ov2 = __shfl_down_sync(0xffffffffu, v2, d);
        int   oi2 = __shfl_down_sync(0xffffffffu, i2, d);
        if (ov1 > v1 || (ov1 == v1 && oi1 < i1)) { v2 = v1; i2 = i1; v1 = ov1; i1 = oi1; }
        else if (ov1 > v2 || (ov1 == v2 && oi1 < i2)) { v2 = ov1; i2 = oi1; }
        if (ov2 > v1 || (ov2 == v1 && oi2 < i1)) { v2 = v1; i2 = i1; v1 = ov2; i1 = oi2; }
        else if (ov2 > v2 || (ov2 == v2 && oi2 < i2)) { v2 = ov2; i2 = oi2; }
    }
    if (lane == 0) { si1[gate] = i1; si2[gate] = i2; }
    __syncthreads();

    if (tid < NGATES) { needf[si1[tid]] = 1; needf[si2[tid]] = 1; }
    __syncthreads();

    if (tid < 32) {                        // two-pool prefix compaction
        int runX = 0;
#pragma unroll
        for (int ch = 0; ch < 2; ++ch) {
            int e = ch * 32 + tid;
            bool nd = needf[e] != 0;
            unsigned mask = __ballot_sync(0xffffffffu, nd);
            xrowA[e] = nd ? (XROW0 + runX + __popc(mask & ((1u << tid) - 1u))) : 0;
            runX += __popc(mask);
        }
        int runG = 0;
#pragma unroll
        for (int ch = 0; ch < 2; ++ch) {
            int g = ch * 32 + tid;
            bool nd = needf[BASEN + g] != 0;
            unsigned mask = __ballot_sync(0xffffffffu, nd);
            growA[g] = nd ? (GROW0 + runG + __popc(mask & ((1u << tid) - 1u))) : 0;
            runG += __popc(mask);
        }
        if (tid == 0)
            g_stage.flags = (runX > CAPX || runG > CAPG) ? 1u : 0u;
    }
    __syncthreads();

    if (tid < NGATES) {
        int e1 = si1[tid], e2 = si2[tid];
        auto enc = [&](int e) -> unsigned {
            if (e < 64)  return (unsigned)(xrowA[e] * ROWB) | 1u;  // X: flag bit0
            if (e == 64) return 1u * ROWB;
            if (e == 65) return 2u * ROWB;
            return (unsigned)(growA[e - BASEN] * ROWB);
        };
        g_stage.goff[tid] = make_uint4(enc(e1), 8u * (unsigned)((e1 >> 2) & 15),
                                       enc(e2), 8u * (unsigned)((e2 >> 2) & 15));
        g_stage.gstore[tid] = growA[tid] ? (unsigned)(growA[tid] * ROWB) : 0u;
        g_stage.forig[tid]  = make_uint2((unsigned)(e1 * FROWB),
                                         (unsigned)(e2 * FROWB));
    }
    if (tid < NFEAT)
        g_stage.xoff[tid] = xrowA[tid] ? (unsigned)(xrowA[tid] * ROWB) : 0u;
    if (tid < NGATES * NOUT) {
        int i = tid >> 3, j = tid & 7;
        float wv = ow[i * NOUT + j] * sc[j];
        g_stage.w2[i][j] = make_float2(wv, wv);
        g_stage.w1[i][j] = wv;
    }
}

static __device__ __forceinline__ unsigned pack_h2(float a, float b) {
    __half2 h = __floats2half2_rn(a, b);
    __half2_raw r = *reinterpret_cast<__half2_raw*>(&h);
    return (unsigned)r.x | ((unsigned)r.y << 16);
}

// ---------------------------------------------------------------------------
// Fast path: persistent blocks, double-buffered X region. The 32 LDG.128 for
// tile t+1 are issued in 4 groups interleaved into the 64-gate loop of tile t
// (issue at gate 16g, pack+STS to the back buffer at gate 16g+15), so DRAM
// stays busy during gate compute instead of bursting between barriers.
// ---------------------------------------------------------------------------
__global__ void __launch_bounds__(BLK, 3)
fast_kernel(const float* __restrict__ X, float* __restrict__ out) {
    if (c_p.flags) return;
    extern __shared__ char sb[];
    const int tid = threadIdx.x;
    const int c  = tid & 15;          // feature chunk: features 4c..4c+3
    const int h  = (tid >> 4) & 1;
    const int wq = tid >> 5;
    const unsigned m   = 4u * tid;    // sample-pair byte offset within a row
    const unsigned swz = 8u * (unsigned)c;

    unsigned xo[4];
#pragma unroll
    for (int f = 0; f < 4; ++f) xo[f] = c_p.xoff[4 * c + f];

    *(__half2*)(sb + 1 * ROWB + m) = __floats2half2_rn(0.0f, 0.0f);
    *(__half2*)(sb + 2 * ROWB + m) = __floats2half2_rn(1.0f, 1.0f);

    // Prologue: load first tile into X buffer 0.
    long long t = blockIdx.x;
    {
        const float4* Xb = (const float4*)(X + t * SPB * NFEAT);
#pragma unroll
        for (int r = 0; r < 8; ++r) {
            int sq = 16 * wq + 8 * h + r;
            const float4* rp = Xb + (4 * sq) * 16 + c;
            float4 v0 = __ldcs(rp + 0 * 16);
            float4 v1 = __ldcs(rp + 1 * 16);
            float4 v2 = __ldcs(rp + 2 * 16);
            float4 v3 = __ldcs(rp + 3 * 16);
            unsigned so = (8u * (unsigned)sq) ^ swz;
            if (xo[0]) *(uint2*)(sb + xo[0] + so) =
                make_uint2(pack_h2(v0.x, v1.x), pack_h2(v2.x, v3.x));
            if (xo[1]) *(uint2*)(sb + xo[1] + so) =
                make_uint2(pack_h2(v0.y, v1.y), pack_h2(v2.y, v3.y));
            if (xo[2]) *(uint2*)(sb + xo[2] + so) =
                make_uint2(pack_h2(v0.z, v1.z), pack_h2(v2.z, v3.z));
            if (xo[3]) *(uint2*)(sb + xo[3] + so) =
                make_uint2(pack_h2(v0.w, v1.w), pack_h2(v2.w, v3.w));
        }
    }
    __syncthreads();

    unsigned phase = 0;
    for (; t < NT; t += GRID_FAST) {
        const long long nt = t + GRID_FAST;
        const bool hn = nt < NT;
        const unsigned phX  = phase ? (unsigned)XSZB : 0u;   // current X buffer add
        const unsigned nphX = phase ? 0u : (unsigned)XSZB;   // next X buffer add
        const float4* Xn = (const float4*)(X + nt * SPB * NFEAT);

        unsigned long long acc[NOUT];
#pragma unroll
        for (int j = 0; j < NOUT; ++j) acc[j] = 0ULL;

        float4 pv[8];                     // in-flight LDG payload (one group)

        uint4 o = c_p.goff[0];
        unsigned aox = (o.x & ~1u) + ((o.x & 1u) ? phX : 0u);
        unsigned aoz = (o.z & ~1u) + ((o.z & 1u) ? phX : 0u);
        __half2 ah = *(const __half2*)(sb + aox + (m ^ o.y));
        __half2 bh = *(const __half2*)(sb + aoz + (m ^ o.w));

#pragma unroll
        for (int i = 0; i < NGATES; ++i) {
            if ((i & 15) == 0 && hn) {    // issue LDG group (i>>4) for tile t+1
                const int grp = i >> 4;
#pragma unroll
                for (int rr = 0; rr < 2; ++rr) {
                    int sq = 16 * wq + 8 * h + 2 * grp + rr;
                    const float4* rp = Xn + (4 * sq) * 16 + c;
                    pv[4 * rr + 0] = __ldcs(rp + 0 * 16);
                    pv[4 * rr + 1] = __ldcs(rp + 1 * 16);
                    pv[4 * rr + 2] = __ldcs(rp + 2 * 16);
                    pv[4 * rr + 3] = __ldcs(rp + 3 * 16);
                }
            }

            float2 af = __half22float2(ah);
            float2 bf = __half22float2(bh);
            float gx = fmaf(-af.x, bf.x, 1.0f);
            float gy = fmaf(-af.y, bf.y, 1.0f);

            unsigned os = c_p.gstore[i];  // 0 => dead gate: skip STS
            const unsigned swzS = 8u * (unsigned)(((BASEN + i) >> 2) & 15);
            if (os) *(__half2*)(sb + os + (m ^ swzS)) = __floats2half2_rn(gx, gy);

            if (i + 1 < NGATES) {         // post-STS prefetch: never stale
                o = c_p.goff[i + 1];
                aox = (o.x & ~1u) + ((o.x & 1u) ? phX : 0u);
                aoz = (o.z & ~1u) + ((o.z & 1u) ? phX : 0u);
                ah = *(const __half2*)(sb + aox + (m ^ o.y));
                bh = *(const __half2*)(sb + aoz + (m ^ o.w));
            }

            unsigned long long gg;
            asm("mov.b64 %0, {%1, %2};" : "=l"(gg) : "f"(gx), "f"(gy));
            const unsigned long long* wp = (const unsigned long long*)&c_p.w2[i][0];
#pragma unroll
            for (int j = 0; j < NOUT; ++j)
                asm("fma.rn.f32x2 %0, %1, %2, %0;" : "+l"(acc[j]) : "l"(gg), "l"(wp[j]));

            if ((i & 15) == 15 && hn) {   // pack + STS group to back buffer
                const int grp = i >> 4;
#pragma unroll
                for (int rr = 0; rr < 2; ++rr) {
                    int sq = 16 * wq + 8 * h + 2 * grp + rr;
                    unsigned so = (8u * (unsigned)sq) ^ swz;
                    char* dst = sb + nphX;
                    const float4 v0 = pv[4 * rr + 0], v1 = pv[4 * rr + 1];
                    const float4 v2 = pv[4 * rr + 2], v3 = pv[4 * rr + 3];
                    if (xo[0]) *(uint2*)(dst + xo[0] + so) =
                        make_uint2(pack_h2(v0.x, v1.x), pack_h2(v2.x, v3.x));
                    if (xo[1]) *(uint2*)(dst + xo[1] + so) =
                        make_uint2(pack_h2(v0.y, v1.y), pack_h2(v2.y, v3.y));
                    if (xo[2]) *(uint2*)(dst + xo[2] + so) =
                        make_uint2(pack_h2(v0.z, v1.z), pack_h2(v2.z, v3.z));
                    if (xo[3]) *(uint2*)(dst + xo[3] + so) =
                        make_uint2(pack_h2(v0.w, v1.w), pack_h2(v2.w, v3.w));
                }
            }
        }

        float s0[NOUT], s1[NOUT];
#pragma unroll
        for (int j = 0; j < NOUT; ++j)
            asm("mov.b64 {%0, %1}, %2;" : "=f"(s0[j]), "=f"(s1[j]) : "l"(acc[j]));
        float4* op = (float4*)(out + (t * SPB + 2 * tid) * NOUT);
        __stcs(&op[0], make_float4(s0[0], s0[1], s0[2], s0[3]));
        __stcs(&op[1], make_float4(s0[4], s0[5], s0[6], s0[7]));
        __stcs(&op[2], make_float4(s1[0], s1[1], s1[2], s1[3]));
        __stcs(&op[3], make_float4(s1[4], s1[5], s1[6], s1[7]));

        __syncthreads();                  // gate rows + back buffer committed
        phase ^= 1;
    }
}

// ---------------------------------------------------------------------------
// Fallback (overflow only; ~never): persistent fp32 full-buffer version.
// ---------------------------------------------------------------------------
__global__ void __launch_bounds__(128, 3)
full_kernel(const float* __restrict__ X, float* __restrict__ out) {
    if (!c_p.flags) return;
    extern __shared__ float sbuf[];
    char* sb = (char*)sbuf;
    const int tid = threadIdx.x;

    for (long long tt = blockIdx.x; tt < NTF; tt += GRID_FULL) {
        const long long base = tt * 128;
        const float4* Xb = (const float4*)(X + base * NFEAT);
#pragma unroll
        for (int k = 0; k < NFEAT / 4; ++k) {
            float4 v = __ldcs(&Xb[k * 128 + tid]);
            int e = 4 * (k * 128 + tid);
            int s = e >> 6;
            int f = e & 63;
            sbuf[(f + 0) * FEST + s] = v.x;
            sbuf[(f + 1) * FEST + s] = v.y;
            sbuf[(f + 2) * FEST + s] = v.z;
            sbuf[(f + 3) * FEST + s] = v.w;
        }
        sbuf[64 * FEST + tid] = 0.0f;
        sbuf[65 * FEST + tid] = 1.0f;
        __syncthreads();

        const unsigned m4 = 4u * tid;
        float acc[NOUT];
#pragma unroll
        for (int j = 0; j < NOUT; ++j) acc[j] = 0.0f;

        uint2 o0 = c_p.forig[0];
        float a = *(const float*)(sb + o0.x + m4);
        float b = *(const float*)(sb + o0.y + m4);
#pragma unroll
        for (int i = 0; i < NGATES; ++i) {
            float g = fmaf(-a, b, 1.0f);
            *(float*)(sb + (unsigned)((BASEN + i) * FROWB) + m4) = g;
            if (i + 1 < NGATES) {
                uint2 o = c_p.forig[i + 1];
                a = *(const float*)(sb + o.x + m4);
                b = *(const float*)(sb + o.y + m4);
            }
#pragma unroll
            for (int j = 0; j < NOUT; ++j)
                acc[j] = fmaf(g, c_p.w1[i][j], acc[j]);
        }
        float4* op = (float4*)(out + (base + tid) * NOUT);
        __stcs(&op[0], make_float4(acc[0], acc[1], acc[2], acc[3]));
        __stcs(&op[1], make_float4(acc[4], acc[5], acc[6], acc[7]));
        __syncthreads();
    }
}

// ---------------------------------------------------------------------------
// Launch: prep -> one constant memcpy -> fast + guarded fallback (4 nodes).
// ---------------------------------------------------------------------------
extern "C" void kernel_launch(void* const* d_in, const int* in_sizes, int n_in,
                              void* d_out, int out_size) {
    const float* X  = (const float*)d_in[0];
    const float* gw = (const float*)d_in[1];
    const float* ow = (const float*)d_in[2];
    const float* sc = (const float*)d_in[3];
    float* out = (float*)d_out;

    cudaFuncSetAttribute((const void*)fast_kernel,
                         cudaFuncAttributeMaxDynamicSharedMemorySize, SMEM_FAST);
    cudaFuncSetAttribute((const void*)full_kernel,
                         cudaFuncAttributeMaxDynamicSharedMemorySize, SMEM_FULL);

    prep_kernel<<<1, 1024>>>(gw, ow, sc);

    void* gp = nullptr;
    cudaGetSymbolAddress(&gp, g_stage);
    cudaMemcpyToSymbolAsync(c_p, gp, sizeof(Params), 0,
                            cudaMemcpyDeviceToDevice, 0);

    fast_kernel<<<GRID_FAST, BLK, SMEM_FAST>>>(X, out);
    full_kernel<<<GRID_FULL, 128, SMEM_FULL>>>(X, out);
}